// round 16
// baseline (speedup 1.0000x reference)
#include <cuda_runtime.h>
#include <math.h>
#include <stdint.h>

#define BATCH 4
#define CIN   512
#define HID   64
#define NCLS  11
#define H1    60
#define W1    80
#define P1    4800
#define H2    30
#define W2    40
#define P2    1200
#define HO    480
#define WO    640
#define PO    307200
#define THRESH 500

#define PROB_ELEMS ((size_t)BATCH*NCLS*PO)
#define SEG_ELEMS  ((size_t)BATCH*PO)

#define TILES1 38            // ceil(4800/128)
#define TILES2 10            // ceil(1200/128)
#define RS_BX  10            // 640/64
#define RS_BY  60            // 480/8

// -------- scratch --------
__device__ float g_f1s[2][BATCH*HID*P1];   // K-split halves (bias/relu in fuse)
__device__ float g_f2s[2][BATCH*HID*P2];
__device__ float g_ls[BATCH*NCLS*P1];
__device__ int g_cnt[36], g_minx[36], g_maxx[36], g_miny[36], g_maxy[36];

__device__ __forceinline__ float2 ffma2(float2 a, float2 b, float2 c) {
    float2 d;
    asm("fma.rn.f32x2 %0, %1, %2, %3;"
        : "=l"(*(unsigned long long*)&d)
        : "l"(*(unsigned long long*)&a),
          "l"(*(unsigned long long*)&b),
          "l"(*(unsigned long long*)&c));
    return d;
}

__device__ __forceinline__ void cp16(uint32_t s, const float* g) {
    asm volatile("cp.async.cg.shared.global [%0], [%1], 16;" :: "r"(s), "l"(g));
}
__device__ __forceinline__ void cp_commit() { asm volatile("cp.async.commit_group;"); }
__device__ __forceinline__ void cp_wait0()  { asm volatile("cp.async.wait_group 0;"); }

// ============================================================
// Stage 1: 1x1 conv GEMM, K-split 2 (R14 champion, frozen).
// Tile: 128 px x 64 oc x 256 ch. 256 threads, 4px x 8oc,
// software-pipelined inner loop.
// ============================================================
__global__ void __launch_bounds__(256)
conv_kernel(const float* __restrict__ f1in, const float* __restrict__ f2in,
            const float* __restrict__ w1, const float* __restrict__ w2)
{
    __shared__ alignas(16) float  As[2][32][128];
    __shared__ alignas(16) float2 Bs[2][32][66];

    const int tid = threadIdx.x;
    const int bx = blockIdx.x, kh = blockIdx.y, b = blockIdx.z;

    if (bx == 0 && kh == 0 && b == 0 && tid < 36) {
        g_cnt[tid] = 0;
        g_minx[tid] = 0x7fffffff; g_maxx[tid] = -1;
        g_miny[tid] = 0x7fffffff; g_maxy[tid] = -1;
    }

    const float* in; const float* w; float* out; int P, p0;
    if (bx < TILES1) { in = f1in; w = w1; out = g_f1s[kh]; P = P1; p0 = bx * 128; }
    else             { in = f2in; w = w2; out = g_f2s[kh]; P = P2; p0 = (bx - TILES1) * 128; }
    const float* inb = in + (size_t)b * CIN * P;
    const int k0base = kh * 256;

    const int lane = tid & 31;
    const int to8  = (tid >> 5) * 8;

    const uint32_t as_base = (uint32_t)__cvta_generic_to_shared(&As[0][0][0]);

    float2 acc[8][2];
#pragma unroll
    for (int j = 0; j < 8; j++) { acc[j][0] = make_float2(0.f,0.f); acc[j][1] = make_float2(0.f,0.f); }

    float br[8];

    // ---- prologue ----
    {
        const int k0 = k0base;
#pragma unroll
        for (int q = 0; q < 4; q++) {
            int l = tid + q * 256;
            int row = l >> 5, c4 = l & 31;
            int px = p0 + c4 * 4; if (px > P - 4) px = P - 4;
            cp16(as_base + (uint32_t)(row * 128 + c4 * 4) * 4,
                 inb + (size_t)(k0 + row) * P + px);
        }
        cp_commit();
#pragma unroll
        for (int q = 0; q < 8; q++) {
            int l = tid + q * 256;
            int o = l >> 5, kk = l & 31;
            br[q] = w[o * CIN + k0 + kk];
        }
#pragma unroll
        for (int q = 0; q < 8; q++) {
            int l = tid + q * 256;
            int o = l >> 5, kk = l & 31;
            Bs[0][kk][o] = make_float2(br[q], br[q]);
        }
        cp_wait0();
        __syncthreads();
    }

#pragma unroll 1
    for (int kb = 0; kb < 8; kb++) {
        const int cb = kb & 1;
        const int nb = cb ^ 1;
        if (kb < 7) {
            const int k0 = k0base + (kb + 1) * 32;
#pragma unroll
            for (int q = 0; q < 4; q++) {
                int l = tid + q * 256;
                int row = l >> 5, c4 = l & 31;
                int px = p0 + c4 * 4; if (px > P - 4) px = P - 4;
                cp16(as_base + (uint32_t)(nb * 32 * 128 + row * 128 + c4 * 4) * 4,
                     inb + (size_t)(k0 + row) * P + px);
            }
            cp_commit();
#pragma unroll
            for (int q = 0; q < 8; q++) {
                int l = tid + q * 256;
                int o = l >> 5, kk = l & 31;
                br[q] = w[o * CIN + k0 + kk];
            }
        }
        // ---- compute on buffer cb: software-pipelined over kk ----
        {
            float4 av_c = *(const float4*)&As[cb][0][lane * 4];
            float4 b0_c = *(const float4*)&Bs[cb][0][to8];
            float4 b1_c = *(const float4*)&Bs[cb][0][to8 + 2];
            float4 b2_c = *(const float4*)&Bs[cb][0][to8 + 4];
            float4 b3_c = *(const float4*)&Bs[cb][0][to8 + 6];
#pragma unroll
            for (int kk = 0; kk < 32; kk++) {
                float4 av_n, b0_n, b1_n, b2_n, b3_n;
                if (kk < 31) {
                    av_n = *(const float4*)&As[cb][kk + 1][lane * 4];
                    b0_n = *(const float4*)&Bs[cb][kk + 1][to8];
                    b1_n = *(const float4*)&Bs[cb][kk + 1][to8 + 2];
                    b2_n = *(const float4*)&Bs[cb][kk + 1][to8 + 4];
                    b3_n = *(const float4*)&Bs[cb][kk + 1][to8 + 6];
                }
                float2 ap0 = make_float2(av_c.x, av_c.y);
                float2 ap1 = make_float2(av_c.z, av_c.w);
                float2 bv[8] = { {b0_c.x,b0_c.y},{b0_c.z,b0_c.w},
                                 {b1_c.x,b1_c.y},{b1_c.z,b1_c.w},
                                 {b2_c.x,b2_c.y},{b2_c.z,b2_c.w},
                                 {b3_c.x,b3_c.y},{b3_c.z,b3_c.w} };
#pragma unroll
                for (int j = 0; j < 8; j++) {
                    acc[j][0] = ffma2(ap0, bv[j], acc[j][0]);
                    acc[j][1] = ffma2(ap1, bv[j], acc[j][1]);
                }
                if (kk < 31) {
                    av_c = av_n; b0_c = b0_n; b1_c = b1_n; b2_c = b2_n; b3_c = b3_n;
                }
            }
        }
        __syncthreads();
        if (kb < 7) {
#pragma unroll
            for (int q = 0; q < 8; q++) {
                int l = tid + q * 256;
                int o = l >> 5, kk = l & 31;
                Bs[nb][kk][o] = make_float2(br[q], br[q]);
            }
            cp_wait0();
            __syncthreads();
        }
    }

    // ---- store partial sums (bias/relu deferred to fuse) ----
    float* outb = out + (size_t)b * HID * P;
    const int px0 = p0 + lane * 4;
    if (px0 < P) {
#pragma unroll
        for (int j = 0; j < 8; j++) {
            int oc = to8 + j;
            *(float4*)&outb[(size_t)oc * P + px0] =
                make_float4(acc[j][0].x, acc[j][0].y, acc[j][1].x, acc[j][1].y);
        }
    }
}

// ============================================================
// Stage 2: logits_small = wc * (relu(f1)+up2(relu(f2))) + bc at 60x80.
// ============================================================
__global__ void __launch_bounds__(256)
fuse_kernel(const float* __restrict__ wc, const float* __restrict__ bc,
            const float* __restrict__ b1, const float* __restrict__ b2)
{
    __shared__ float s_wc[NCLS * HID];
    __shared__ float s_b1[HID], s_b2[HID], s_bc[NCLS];
    const int tid = threadIdx.x;
    for (int i = tid; i < NCLS * HID; i += 256) s_wc[i] = wc[i];
    if (tid < HID) { s_b1[tid] = b1[tid]; s_b2[tid] = b2[tid]; }
    if (tid < NCLS) s_bc[tid] = bc[tid];
    __syncthreads();

    const int pl = tid >> 1;
    const int hh = (tid & 1) * 32;
    const int p = blockIdx.x * 128 + pl;
    const int b = blockIdx.y;
    const bool valid = (p < P1);
    const int pp = valid ? p : P1 - 1;
    const int y = pp / W1, x = pp % W1;

    float fx = 0.5f * x - 0.25f;
    int ix0 = (int)floorf(fx); float tx = fx - (float)ix0;
    int ix0c = max(ix0, 0), ix1c = min(ix0 + 1, W2 - 1);
    float fy = 0.5f * y - 0.25f;
    int iy0 = (int)floorf(fy); float ty = fy - (float)iy0;
    int iy0c = max(iy0, 0), iy1c = min(iy0 + 1, H2 - 1);
    int i00 = iy0c * W2 + ix0c, i01 = iy0c * W2 + ix1c;
    int i10 = iy1c * W2 + ix0c, i11 = iy1c * W2 + ix1c;

    const float* f1a = g_f1s[0] + (size_t)b * HID * P1 + pp;
    const float* f1b = g_f1s[1] + (size_t)b * HID * P1 + pp;
    const float* f2a = g_f2s[0] + (size_t)b * HID * P2;
    const float* f2b = g_f2s[1] + (size_t)b * HID * P2;

    float acc[NCLS];
#pragma unroll
    for (int c = 0; c < NCLS; c++) acc[c] = 0.f;

#pragma unroll 4
    for (int h = hh; h < hh + 32; h++) {
        float s = fmaxf(f1a[(size_t)h * P1] + f1b[(size_t)h * P1] + s_b1[h], 0.f);
        const float* ca = f2a + (size_t)h * P2;
        const float* cb2 = f2b + (size_t)h * P2;
        float bb = s_b2[h];
        float v00 = fmaxf(ca[i00] + cb2[i00] + bb, 0.f);
        float v01 = fmaxf(ca[i01] + cb2[i01] + bb, 0.f);
        float v10 = fmaxf(ca[i10] + cb2[i10] + bb, 0.f);
        float v11 = fmaxf(ca[i11] + cb2[i11] + bb, 0.f);
        float v0 = v00 + tx * (v01 - v00);
        float v1 = v10 + tx * (v11 - v10);
        s += v0 + ty * (v1 - v0);
#pragma unroll
        for (int c = 0; c < NCLS; c++) acc[c] = fmaf(s_wc[c * HID + h], s, acc[c]);
    }

#pragma unroll
    for (int c = 0; c < NCLS; c++)
        acc[c] += __shfl_xor_sync(0xffffffffu, acc[c], 1);

    if ((tid & 1) == 0 && valid) {
        float* lsb = g_ls + (size_t)b * NCLS * P1 + p;
#pragma unroll
        for (int c = 0; c < NCLS; c++) lsb[(size_t)c * P1] = acc[c] + s_bc[c];
    }
}

// ============================================================
// Stage 3: resize8 -> softmax -> prob + seg + bbox reduce.
// Index-lean staging: [3][NCLS][16] padded tile, shift/mask indexing,
// row clamps hoisted out of the element loop.
// ============================================================
__global__ void __launch_bounds__(256, 4)
resize_kernel(float* __restrict__ out)
{
    __shared__ float st[3][NCLS][16];
    __shared__ int s_cnt[9], s_minx[9], s_maxx[9], s_miny[9], s_maxy[9];

    const int tx0 = threadIdx.x, ty0 = threadIdx.y;
    const int tid = ty0 * 32 + tx0;
    if (tid < 9) {
        s_cnt[tid] = 0;
        s_minx[tid] = 0x7fffffff; s_maxx[tid] = -1;
        s_miny[tid] = 0x7fffffff; s_maxy[tid] = -1;
    }

    const int bx = blockIdx.x, by = blockIdx.y, b = blockIdx.z;
    const float* ls = g_ls + (size_t)b * NCLS * P1;
    const int colbase = bx * 8 - 1;

#pragma unroll
    for (int r = 0; r < 3; r++) {
        const int row = min(max(by - 1 + r, 0), H1 - 1);
        const float* lr = ls + row * W1;
        // NCLS*16 = 176 <= 256: one element per thread, k>=10 lanes idle
        if (tid < NCLS * 16) {
            int c = tid >> 4, k = tid & 15;
            if (k < 10) {
                int col = min(max(colbase + k, 0), W1 - 1);
                st[r][c][k] = lr[(size_t)c * P1 + col];
            }
        }
    }
    __syncthreads();

    const int u  = tx0 * 2;            // local x of first px (even)
    const int X  = bx * 64 + u;
    const int Y  = by * 8 + ty0;
    const int k0 = (u + 4) >> 3;       // shared source col pair (k0, k0+1)
    const int r0 = (ty0 < 4) ? 0 : 1;
    const float ty = (ty0 < 4) ? (float)(2 * ty0 + 9) * (1.f / 16.f)
                               : (float)(2 * ty0 - 7) * (1.f / 16.f);
    float txw[2];
#pragma unroll
    for (int j = 0; j < 2; j++) {
        int jx = (u + j) & 7;
        txw[j] = (jx < 4) ? (float)(2 * jx + 9) * (1.f / 16.f)
                          : (float)(2 * jx - 7) * (1.f / 16.f);
    }

    float Av[NCLS], Dv[NCLS];
#pragma unroll
    for (int c = 0; c < NCLS; c++) {
        float a0 = st[r0][c][k0],     b0v = st[r0][c][k0 + 1];
        float a1 = st[r0 + 1][c][k0], b1v = st[r0 + 1][c][k0 + 1];
        float A = a0 + ty * (a1 - a0);
        float B = b0v + ty * (b1v - b0v);
        Av[c] = A; Dv[c] = B - A;
    }

    float e[2][NCLS];
    int arg[2];
    float inv[2];
#pragma unroll
    for (int j = 0; j < 2; j++) {
        float mm = -1e30f; int aa = 0;
#pragma unroll
        for (int c = 0; c < NCLS; c++) {
            float v = fmaf(txw[j], Dv[c], Av[c]);
            e[j][c] = v;
            if (v > mm) { mm = v; aa = c; }
        }
        arg[j] = aa;
        float s = 0.f;
#pragma unroll
        for (int c = 0; c < NCLS; c++) {
            float ex = __expf(e[j][c] - mm);
            e[j][c] = ex; s += ex;
        }
        inv[j] = 1.f / s;
    }

    const size_t base = (size_t)b * NCLS * PO + (size_t)Y * WO + X;
#pragma unroll
    for (int c = 0; c < NCLS; c++) {
        float2 v2 = make_float2(e[0][c] * inv[0], e[1][c] * inv[1]);
        *(float2*)&out[base + (size_t)c * PO] = v2;
    }
    *(float2*)&out[PROB_ELEMS + (size_t)b * PO + (size_t)Y * WO + X] =
        make_float2((float)arg[0], (float)arg[1]);

    if (arg[0] == arg[1]) {
        int c = arg[0];
        if (c >= 1 && c <= 9) {
            int k = c - 1;
            atomicAdd(&s_cnt[k], 2);
            atomicMin(&s_minx[k], X); atomicMax(&s_maxx[k], X + 1);
            atomicMin(&s_miny[k], Y); atomicMax(&s_maxy[k], Y);
        }
    } else {
#pragma unroll
        for (int j = 0; j < 2; j++) {
            int c = arg[j];
            if (c >= 1 && c <= 9) {
                int k = c - 1;
                atomicAdd(&s_cnt[k], 1);
                atomicMin(&s_minx[k], X + j); atomicMax(&s_maxx[k], X + j);
                atomicMin(&s_miny[k], Y);     atomicMax(&s_maxy[k], Y);
            }
        }
    }
    __syncthreads();
    if (tid < 9 && s_cnt[tid] > 0) {
        int g = b * 9 + tid;
        atomicAdd(&g_cnt[g], s_cnt[tid]);
        atomicMin(&g_minx[g], s_minx[tid]); atomicMax(&g_maxx[g], s_maxx[tid]);
        atomicMin(&g_miny[g], s_miny[tid]); atomicMax(&g_maxy[g], s_maxy[tid]);
    }
}

// ============================================================
// Stage 4: bbox finalize (1 block).
// ============================================================
__global__ void finalize_kernel(float* __restrict__ out)
{
    int t = threadIdx.x;
    if (t >= 36) return;
    float* row = out + PROB_ELEMS + SEG_ELEMS + (size_t)t * 6;
    if (g_cnt[t] >= THRESH) {
        row[0] = (float)(t / 9);
        row[1] = (float)g_minx[t];
        row[2] = (float)g_miny[t];
        row[3] = (float)g_maxx[t];
        row[4] = (float)g_maxy[t];
        row[5] = (float)(t % 9 + 1);
    } else {
        row[0] = -1.f; row[1] = -1.f; row[2] = -1.f;
        row[3] = -1.f; row[4] = -1.f; row[5] = -1.f;
    }
}

// ============================================================
extern "C" void kernel_launch(void* const* d_in, const int* in_sizes, int n_in,
                              void* d_out, int out_size)
{
    const float* feature1 = (const float*)d_in[0];
    const float* feature2 = (const float*)d_in[1];
    const float* w1 = (const float*)d_in[2];
    const float* b1 = (const float*)d_in[3];
    const float* w2 = (const float*)d_in[4];
    const float* b2 = (const float*)d_in[5];
    const float* wc = (const float*)d_in[6];
    const float* bc = (const float*)d_in[7];
    float* out = (float*)d_out;

    conv_kernel<<<dim3(TILES1 + TILES2, 2, BATCH), 256>>>(feature1, feature2, w1, w2);
    fuse_kernel<<<dim3(38, BATCH), 256>>>(wc, bc, b1, b2);
    resize_kernel<<<dim3(RS_BX, RS_BY, BATCH), dim3(32, 8)>>>(out);
    finalize_kernel<<<1, 36>>>(out);
}

// round 17
// speedup vs baseline: 1.4993x; 1.4993x over previous
#include <cuda_runtime.h>
#include <math.h>
#include <stdint.h>

#define BATCH 4
#define CIN   512
#define HID   64
#define NCLS  11
#define H1    60
#define W1    80
#define P1    4800
#define H2    30
#define W2    40
#define P2    1200
#define HO    480
#define WO    640
#define PO    307200
#define THRESH 500

#define PROB_ELEMS ((size_t)BATCH*NCLS*PO)
#define SEG_ELEMS  ((size_t)BATCH*PO)

#define TILES1 38            // ceil(4800/128)
#define TILES2 10            // ceil(1200/128)
#define RS_BX  10            // 640/64
#define RS_BY  60            // 480/8

// -------- scratch --------
__device__ float g_f1s[2][BATCH*HID*P1];   // K-split halves (bias/relu in fuse)
__device__ float g_f2s[2][BATCH*HID*P2];
__device__ float g_ls[BATCH*NCLS*P1];
__device__ int g_cnt[36], g_minx[36], g_maxx[36], g_miny[36], g_maxy[36];

__device__ __forceinline__ float2 ffma2(float2 a, float2 b, float2 c) {
    float2 d;
    asm("fma.rn.f32x2 %0, %1, %2, %3;"
        : "=l"(*(unsigned long long*)&d)
        : "l"(*(unsigned long long*)&a),
          "l"(*(unsigned long long*)&b),
          "l"(*(unsigned long long*)&c));
    return d;
}

__device__ __forceinline__ void cp16(uint32_t s, const float* g) {
    asm volatile("cp.async.cg.shared.global [%0], [%1], 16;" :: "r"(s), "l"(g));
}
__device__ __forceinline__ void cp_commit() { asm volatile("cp.async.commit_group;"); }
__device__ __forceinline__ void cp_wait0()  { asm volatile("cp.async.wait_group 0;"); }

// ============================================================
// Stage 1: 1x1 conv GEMM, K-split 2 (champion body, frozen).
// Tile: 128 px x 64 oc x 256 ch. 256 threads, 4px x 8oc,
// software-pipelined inner loop.
// ============================================================
__global__ void __launch_bounds__(256)
conv_kernel(const float* __restrict__ f1in, const float* __restrict__ f2in,
            const float* __restrict__ w1, const float* __restrict__ w2)
{
    __shared__ alignas(16) float  As[2][32][128];
    __shared__ alignas(16) float2 Bs[2][32][66];

    const int tid = threadIdx.x;
    const int bx = blockIdx.x, kh = blockIdx.y, b = blockIdx.z;

    if (bx == 0 && kh == 0 && b == 0 && tid < 36) {
        g_cnt[tid] = 0;
        g_minx[tid] = 0x7fffffff; g_maxx[tid] = -1;
        g_miny[tid] = 0x7fffffff; g_maxy[tid] = -1;
    }

    const float* in; const float* w; float* out; int P, p0;
    if (bx < TILES1) { in = f1in; w = w1; out = g_f1s[kh]; P = P1; p0 = bx * 128; }
    else             { in = f2in; w = w2; out = g_f2s[kh]; P = P2; p0 = (bx - TILES1) * 128; }
    const float* inb = in + (size_t)b * CIN * P;
    const int k0base = kh * 256;

    const int lane = tid & 31;          // pixel group: px = p0 + lane*4
    const int to8  = (tid >> 5) * 8;    // oc group (warp-uniform)

    const uint32_t as_base = (uint32_t)__cvta_generic_to_shared(&As[0][0][0]);

    float2 acc[8][2];
#pragma unroll
    for (int j = 0; j < 8; j++) { acc[j][0] = make_float2(0.f,0.f); acc[j][1] = make_float2(0.f,0.f); }

    float br[8];

    // ---- prologue ----
    {
        const int k0 = k0base;
#pragma unroll
        for (int q = 0; q < 4; q++) {
            int l = tid + q * 256;
            int row = l >> 5, c4 = l & 31;
            int px = p0 + c4 * 4; if (px > P - 4) px = P - 4;
            cp16(as_base + (uint32_t)(row * 128 + c4 * 4) * 4,
                 inb + (size_t)(k0 + row) * P + px);
        }
        cp_commit();
#pragma unroll
        for (int q = 0; q < 8; q++) {
            int l = tid + q * 256;
            int o = l >> 5, kk = l & 31;
            br[q] = w[o * CIN + k0 + kk];
        }
#pragma unroll
        for (int q = 0; q < 8; q++) {
            int l = tid + q * 256;
            int o = l >> 5, kk = l & 31;
            Bs[0][kk][o] = make_float2(br[q], br[q]);
        }
        cp_wait0();
        __syncthreads();
    }

#pragma unroll 1
    for (int kb = 0; kb < 8; kb++) {
        const int cb = kb & 1;
        const int nb = cb ^ 1;
        if (kb < 7) {
            const int k0 = k0base + (kb + 1) * 32;
#pragma unroll
            for (int q = 0; q < 4; q++) {
                int l = tid + q * 256;
                int row = l >> 5, c4 = l & 31;
                int px = p0 + c4 * 4; if (px > P - 4) px = P - 4;
                cp16(as_base + (uint32_t)(nb * 32 * 128 + row * 128 + c4 * 4) * 4,
                     inb + (size_t)(k0 + row) * P + px);
            }
            cp_commit();
#pragma unroll
            for (int q = 0; q < 8; q++) {
                int l = tid + q * 256;
                int o = l >> 5, kk = l & 31;
                br[q] = w[o * CIN + k0 + kk];
            }
        }
        // ---- compute on buffer cb: software-pipelined over kk ----
        {
            float4 av_c = *(const float4*)&As[cb][0][lane * 4];
            float4 b0_c = *(const float4*)&Bs[cb][0][to8];
            float4 b1_c = *(const float4*)&Bs[cb][0][to8 + 2];
            float4 b2_c = *(const float4*)&Bs[cb][0][to8 + 4];
            float4 b3_c = *(const float4*)&Bs[cb][0][to8 + 6];
#pragma unroll
            for (int kk = 0; kk < 32; kk++) {
                float4 av_n, b0_n, b1_n, b2_n, b3_n;
                if (kk < 31) {
                    av_n = *(const float4*)&As[cb][kk + 1][lane * 4];
                    b0_n = *(const float4*)&Bs[cb][kk + 1][to8];
                    b1_n = *(const float4*)&Bs[cb][kk + 1][to8 + 2];
                    b2_n = *(const float4*)&Bs[cb][kk + 1][to8 + 4];
                    b3_n = *(const float4*)&Bs[cb][kk + 1][to8 + 6];
                }
                float2 ap0 = make_float2(av_c.x, av_c.y);
                float2 ap1 = make_float2(av_c.z, av_c.w);
                float2 bv[8] = { {b0_c.x,b0_c.y},{b0_c.z,b0_c.w},
                                 {b1_c.x,b1_c.y},{b1_c.z,b1_c.w},
                                 {b2_c.x,b2_c.y},{b2_c.z,b2_c.w},
                                 {b3_c.x,b3_c.y},{b3_c.z,b3_c.w} };
#pragma unroll
                for (int j = 0; j < 8; j++) {
                    acc[j][0] = ffma2(ap0, bv[j], acc[j][0]);
                    acc[j][1] = ffma2(ap1, bv[j], acc[j][1]);
                }
                if (kk < 31) {
                    av_c = av_n; b0_c = b0_n; b1_c = b1_n; b2_c = b2_n; b3_c = b3_n;
                }
            }
        }
        __syncthreads();
        if (kb < 7) {
#pragma unroll
            for (int q = 0; q < 8; q++) {
                int l = tid + q * 256;
                int o = l >> 5, kk = l & 31;
                Bs[nb][kk][o] = make_float2(br[q], br[q]);
            }
            cp_wait0();
            __syncthreads();
        }
    }

    // ---- store partial sums (bias/relu deferred to fuse) ----
    float* outb = out + (size_t)b * HID * P;
    const int px0 = p0 + lane * 4;
    if (px0 < P) {
#pragma unroll
        for (int j = 0; j < 8; j++) {
            int oc = to8 + j;
            *(float4*)&outb[(size_t)oc * P + px0] =
                make_float4(acc[j][0].x, acc[j][0].y, acc[j][1].x, acc[j][1].y);
        }
    }
}

// ============================================================
// Stage 2: logits_small = wc * (relu(f1)+up2(relu(f2))) + bc at 60x80.
// ============================================================
__global__ void __launch_bounds__(256)
fuse_kernel(const float* __restrict__ wc, const float* __restrict__ bc,
            const float* __restrict__ b1, const float* __restrict__ b2)
{
    __shared__ float s_wc[NCLS * HID];
    __shared__ float s_b1[HID], s_b2[HID], s_bc[NCLS];
    const int tid = threadIdx.x;
    for (int i = tid; i < NCLS * HID; i += 256) s_wc[i] = wc[i];
    if (tid < HID) { s_b1[tid] = b1[tid]; s_b2[tid] = b2[tid]; }
    if (tid < NCLS) s_bc[tid] = bc[tid];
    __syncthreads();

    const int pl = tid >> 1;
    const int hh = (tid & 1) * 32;
    const int p = blockIdx.x * 128 + pl;
    const int b = blockIdx.y;
    const bool valid = (p < P1);
    const int pp = valid ? p : P1 - 1;
    const int y = pp / W1, x = pp % W1;

    float fx = 0.5f * x - 0.25f;
    int ix0 = (int)floorf(fx); float tx = fx - (float)ix0;
    int ix0c = max(ix0, 0), ix1c = min(ix0 + 1, W2 - 1);
    float fy = 0.5f * y - 0.25f;
    int iy0 = (int)floorf(fy); float ty = fy - (float)iy0;
    int iy0c = max(iy0, 0), iy1c = min(iy0 + 1, H2 - 1);
    int i00 = iy0c * W2 + ix0c, i01 = iy0c * W2 + ix1c;
    int i10 = iy1c * W2 + ix0c, i11 = iy1c * W2 + ix1c;

    const float* f1a = g_f1s[0] + (size_t)b * HID * P1 + pp;
    const float* f1b = g_f1s[1] + (size_t)b * HID * P1 + pp;
    const float* f2a = g_f2s[0] + (size_t)b * HID * P2;
    const float* f2b = g_f2s[1] + (size_t)b * HID * P2;

    float acc[NCLS];
#pragma unroll
    for (int c = 0; c < NCLS; c++) acc[c] = 0.f;

#pragma unroll 4
    for (int h = hh; h < hh + 32; h++) {
        float s = fmaxf(f1a[(size_t)h * P1] + f1b[(size_t)h * P1] + s_b1[h], 0.f);
        const float* ca = f2a + (size_t)h * P2;
        const float* cb2 = f2b + (size_t)h * P2;
        float bb = s_b2[h];
        float v00 = fmaxf(ca[i00] + cb2[i00] + bb, 0.f);
        float v01 = fmaxf(ca[i01] + cb2[i01] + bb, 0.f);
        float v10 = fmaxf(ca[i10] + cb2[i10] + bb, 0.f);
        float v11 = fmaxf(ca[i11] + cb2[i11] + bb, 0.f);
        float v0 = v00 + tx * (v01 - v00);
        float v1 = v10 + tx * (v11 - v10);
        s += v0 + ty * (v1 - v0);
#pragma unroll
        for (int c = 0; c < NCLS; c++) acc[c] = fmaf(s_wc[c * HID + h], s, acc[c]);
    }

#pragma unroll
    for (int c = 0; c < NCLS; c++)
        acc[c] += __shfl_xor_sync(0xffffffffu, acc[c], 1);

    if ((tid & 1) == 0 && valid) {
        float* lsb = g_ls + (size_t)b * NCLS * P1 + p;
#pragma unroll
        for (int c = 0; c < NCLS; c++) lsb[(size_t)c * P1] = acc[c] + s_bc[c];
    }
}

// ============================================================
// Stage 3: resize8 -> softmax -> prob + seg + bbox reduce (champion, frozen).
// ============================================================
__global__ void __launch_bounds__(256, 4)
resize_kernel(float* __restrict__ out)
{
    __shared__ float st[NCLS][3][10];
    __shared__ int s_cnt[9], s_minx[9], s_maxx[9], s_miny[9], s_maxy[9];

    const int tx0 = threadIdx.x, ty0 = threadIdx.y;
    const int tid = ty0 * 32 + tx0;
    if (tid < 9) {
        s_cnt[tid] = 0;
        s_minx[tid] = 0x7fffffff; s_maxx[tid] = -1;
        s_miny[tid] = 0x7fffffff; s_maxy[tid] = -1;
    }

    const int bx = blockIdx.x, by = blockIdx.y, b = blockIdx.z;
    const float* ls = g_ls + (size_t)b * NCLS * P1;

    for (int i = tid; i < NCLS * 3 * 10; i += 256) {
        int c = i / 30; int rk = i % 30; int r = rk / 10; int k = rk % 10;
        int col = min(max(bx * 8 - 1 + k, 0), W1 - 1);
        int row = min(max(by - 1 + r, 0), H1 - 1);
        st[c][r][k] = ls[(size_t)c * P1 + row * W1 + col];
    }
    __syncthreads();

    const int u  = tx0 * 2;            // local x of first px (even)
    const int X  = bx * 64 + u;
    const int Y  = by * 8 + ty0;
    const int k0 = (u + 4) >> 3;       // shared source col pair (k0, k0+1)
    const int r0 = (ty0 < 4) ? 0 : 1;
    const float ty = (ty0 < 4) ? (float)(2 * ty0 + 9) * (1.f / 16.f)
                               : (float)(2 * ty0 - 7) * (1.f / 16.f);
    float txw[2];
#pragma unroll
    for (int j = 0; j < 2; j++) {
        int jx = (u + j) & 7;
        txw[j] = (jx < 4) ? (float)(2 * jx + 9) * (1.f / 16.f)
                          : (float)(2 * jx - 7) * (1.f / 16.f);
    }

    float Av[NCLS], Dv[NCLS];
#pragma unroll
    for (int c = 0; c < NCLS; c++) {
        float a0 = st[c][r0][k0],     b0v = st[c][r0][k0 + 1];
        float a1 = st[c][r0 + 1][k0], b1v = st[c][r0 + 1][k0 + 1];
        float A = a0 + ty * (a1 - a0);
        float B = b0v + ty * (b1v - b0v);
        Av[c] = A; Dv[c] = B - A;
    }

    float e[2][NCLS];
    int arg[2];
    float inv[2];
#pragma unroll
    for (int j = 0; j < 2; j++) {
        float mm = -1e30f; int aa = 0;
#pragma unroll
        for (int c = 0; c < NCLS; c++) {
            float v = fmaf(txw[j], Dv[c], Av[c]);
            e[j][c] = v;
            if (v > mm) { mm = v; aa = c; }
        }
        arg[j] = aa;
        float s = 0.f;
#pragma unroll
        for (int c = 0; c < NCLS; c++) {
            float ex = __expf(e[j][c] - mm);
            e[j][c] = ex; s += ex;
        }
        inv[j] = 1.f / s;
    }

    const size_t base = (size_t)b * NCLS * PO + (size_t)Y * WO + X;
#pragma unroll
    for (int c = 0; c < NCLS; c++) {
        float2 v2 = make_float2(e[0][c] * inv[0], e[1][c] * inv[1]);
        *(float2*)&out[base + (size_t)c * PO] = v2;
    }
    *(float2*)&out[PROB_ELEMS + (size_t)b * PO + (size_t)Y * WO + X] =
        make_float2((float)arg[0], (float)arg[1]);

    if (arg[0] == arg[1]) {
        int c = arg[0];
        if (c >= 1 && c <= 9) {
            int k = c - 1;
            atomicAdd(&s_cnt[k], 2);
            atomicMin(&s_minx[k], X); atomicMax(&s_maxx[k], X + 1);
            atomicMin(&s_miny[k], Y); atomicMax(&s_maxy[k], Y);
        }
    } else {
#pragma unroll
        for (int j = 0; j < 2; j++) {
            int c = arg[j];
            if (c >= 1 && c <= 9) {
                int k = c - 1;
                atomicAdd(&s_cnt[k], 1);
                atomicMin(&s_minx[k], X + j); atomicMax(&s_maxx[k], X + j);
                atomicMin(&s_miny[k], Y);     atomicMax(&s_maxy[k], Y);
            }
        }
    }
    __syncthreads();
    if (tid < 9 && s_cnt[tid] > 0) {
        int g = b * 9 + tid;
        atomicAdd(&g_cnt[g], s_cnt[tid]);
        atomicMin(&g_minx[g], s_minx[tid]); atomicMax(&g_maxx[g], s_maxx[tid]);
        atomicMin(&g_miny[g], s_miny[tid]); atomicMax(&g_maxy[g], s_maxy[tid]);
    }
}

// ============================================================
// Stage 4: bbox finalize (1 block).
// ============================================================
__global__ void finalize_kernel(float* __restrict__ out)
{
    int t = threadIdx.x;
    if (t >= 36) return;
    float* row = out + PROB_ELEMS + SEG_ELEMS + (size_t)t * 6;
    if (g_cnt[t] >= THRESH) {
        row[0] = (float)(t / 9);
        row[1] = (float)g_minx[t];
        row[2] = (float)g_miny[t];
        row[3] = (float)g_maxx[t];
        row[4] = (float)g_maxy[t];
        row[5] = (float)(t % 9 + 1);
    } else {
        row[0] = -1.f; row[1] = -1.f; row[2] = -1.f;
        row[3] = -1.f; row[4] = -1.f; row[5] = -1.f;
    }
}

// ============================================================
extern "C" void kernel_launch(void* const* d_in, const int* in_sizes, int n_in,
                              void* d_out, int out_size)
{
    const float* feature1 = (const float*)d_in[0];
    const float* feature2 = (const float*)d_in[1];
    const float* w1 = (const float*)d_in[2];
    const float* b1 = (const float*)d_in[3];
    const float* w2 = (const float*)d_in[4];
    const float* b2 = (const float*)d_in[5];
    const float* wc = (const float*)d_in[6];
    const float* bc = (const float*)d_in[7];
    float* out = (float*)d_out;

    conv_kernel<<<dim3(TILES1 + TILES2, 2, BATCH), 256>>>(feature1, feature2, w1, w2);
    fuse_kernel<<<dim3(38, BATCH), 256>>>(wc, bc, b1, b2);
    resize_kernel<<<dim3(RS_BX, RS_BY, BATCH), dim3(32, 8)>>>(out);
    finalize_kernel<<<1, 64>>>(out);
}